// round 9
// baseline (speedup 1.0000x reference)
#include <cuda_runtime.h>
#include <cstdint>

#define H 128
#define MAXN 102400

// ---------------- scratch (device globals = sanctioned scratch) ----------------
__device__ float g_agg[(size_t)MAXN * H];
__device__ float g_h1[(size_t)MAXN * H];
__device__ uint4 g_wf1[32 * 8 * 32];  // K=256: s=32, u2=8, lane=32  (128KB)
__device__ uint4 g_wf2[16 * 8 * 32];  // K=128
__device__ uint4 g_wf3[16 * 8 * 32];

__device__ __forceinline__ unsigned f2tf32(float x) {
    unsigned r;
    asm volatile("cvt.rna.tf32.f32 %0, %1;" : "=r"(r) : "f"(x));
    return r;
}

__device__ __forceinline__ void mma_tf32(float c[4], const unsigned a[4], const unsigned b[2]) {
    asm volatile(
        "mma.sync.aligned.m16n8k8.row.col.f32.tf32.tf32.f32 "
        "{%0,%1,%2,%3}, {%4,%5,%6,%7}, {%8,%9}, {%0,%1,%2,%3};"
        : "+f"(c[0]), "+f"(c[1]), "+f"(c[2]), "+f"(c[3])
        : "r"(a[0]), "r"(a[1]), "r"(a[2]), "r"(a[3]), "r"(b[0]), "r"(b[1]));
}

// ---------------- weight pre-pack: W [K,128] row-major -> B fragments ----------------
__global__ void wpack_kernel(const float* __restrict__ W, uint4* __restrict__ Wf, int K) {
    int idx = blockIdx.x * blockDim.x + threadIdx.x;
    int total = (K / 8) * 8 * 32;
    if (idx >= total) return;
    int lane = idx & 31;
    int u2 = (idx >> 5) & 7;
    int s = idx >> 8;
    int n_e = u2 * 16 + (lane >> 2);
    int n_o = n_e + 8;
    int k = s * 8 + (lane & 3);
    uint4 v;
    v.x = f2tf32(W[(long long)k * H + n_e]);
    v.y = f2tf32(W[(long long)(k + 4) * H + n_e]);
    v.z = f2tf32(W[(long long)k * H + n_o]);
    v.w = f2tf32(W[(long long)(k + 4) * H + n_o]);
    Wf[idx] = v;
}

// ---------------- scatter: one warp per edge, red.v4 per lane (R4 config) ----------------
__global__ void scatter_kernel(const float* __restrict__ ea,
                               const int* __restrict__ ei,
                               float* __restrict__ agg, int E) {
    long long idx = (long long)blockIdx.x * blockDim.x + threadIdx.x;
    int e = (int)(idx >> 5);
    if (e >= E) return;
    int c = ((int)idx & 31) << 2;
    int col = ei[E + e];  // edge_index[1][e] (int32)
    const float4 v = *reinterpret_cast<const float4*>(ea + (long long)e * H + c);
    float* dst = agg + (long long)col * H + c;
    asm volatile("red.global.add.v4.f32 [%0], {%1, %2, %3, %4};"
                 :: "l"(dst), "f"(v.x), "f"(v.y), "f"(v.z), "f"(v.w) : "memory");
}

// ---------------- fused layer: smem-free mma.sync GEMM + bias + LN + ssp ----------------
// 256 threads = 8 warps. Warp owns 16 rows x 64 cols (warp pairs split N).
// CTA tile = 64 rows x 128 cols. acc = 32 regs/thread -> 3 CTAs/SM.
template <int S, bool CONCAT>
__global__ __launch_bounds__(256, 3) void layer_mma(
    const float* __restrict__ a0src, const float* __restrict__ a1src,
    const uint4* __restrict__ Wf,
    const float* __restrict__ bias, const float* __restrict__ gamma,
    const float* __restrict__ beta, float* __restrict__ out, int N) {
    __shared__ float2 sred[64][2];
    const int tid = threadIdx.x;
    const int w = tid >> 5;
    const int lane = tid & 31;
    const int t4 = lane & 3;
    const int wp = w >> 1;   // row group 0..3
    const int wh = w & 1;    // col half 0..1
    const int m0 = blockIdx.x * 64 + wp * 16;
    const int r0 = m0 + (lane >> 2);
    const int r1 = r0 + 8;
    const long long r0c = (long long)min(r0, N - 1) * H;
    const long long r1c = (long long)min(r1, N - 1) * H;

    float acc[8][4];
#pragma unroll
    for (int u = 0; u < 8; ++u)
#pragma unroll
        for (int j = 0; j < 4; ++j) acc[u][j] = 0.f;

#pragma unroll
    for (int s = 0; s < S; ++s) {
        const float* src;
        int kb;
        if (CONCAT && s >= 16) { src = a1src; kb = s * 8 - 128; }
        else                   { src = a0src; kb = s * 8; }
        unsigned a[4];
        a[0] = f2tf32(__ldg(src + r0c + kb + t4));
        a[1] = f2tf32(__ldg(src + r1c + kb + t4));
        a[2] = f2tf32(__ldg(src + r0c + kb + t4 + 4));
        a[3] = f2tf32(__ldg(src + r1c + kb + t4 + 4));
        const uint4* wf = Wf + (s * 8 + wh * 4) * 32 + lane;
#pragma unroll
        for (int j = 0; j < 4; ++j) {
            const uint4 bb = __ldg(wf + j * 32);
            unsigned b0[2] = {bb.x, bb.y};
            unsigned b1[2] = {bb.z, bb.w};
            mma_tf32(acc[j * 2], a, b0);
            mma_tf32(acc[j * 2 + 1], a, b1);
        }
    }

    // ---- epilogue: bias + LN (quad shuffle + 2-way cross-warp combine) + ssp ----
    const float LN2 = 0.69314718055994531f;
    const float inv = 1.f / (float)H;
    float s1a = 0.f, s2a = 0.f, s1b = 0.f, s2b = 0.f;
#pragma unroll
    for (int u = 0; u < 8; ++u) {
        int cb = (wh * 4 + (u >> 1)) * 16 + (u & 1) * 8 + t4 * 2;
        const float2 b2 = *reinterpret_cast<const float2*>(bias + cb);
        acc[u][0] += b2.x; acc[u][1] += b2.y;
        acc[u][2] += b2.x; acc[u][3] += b2.y;
        s1a += acc[u][0] + acc[u][1];
        s2a += acc[u][0] * acc[u][0] + acc[u][1] * acc[u][1];
        s1b += acc[u][2] + acc[u][3];
        s2b += acc[u][2] * acc[u][2] + acc[u][3] * acc[u][3];
    }
#pragma unroll
    for (int off = 1; off <= 2; off <<= 1) {
        s1a += __shfl_xor_sync(0xffffffffu, s1a, off);
        s2a += __shfl_xor_sync(0xffffffffu, s2a, off);
        s1b += __shfl_xor_sync(0xffffffffu, s1b, off);
        s2b += __shfl_xor_sync(0xffffffffu, s2b, off);
    }
    const int rowl0 = wp * 16 + (lane >> 2);
    if (t4 == 0) {
        sred[rowl0][wh] = make_float2(s1a, s2a);
        sred[rowl0 + 8][wh] = make_float2(s1b, s2b);
    }
    __syncthreads();
    float2 p00 = sred[rowl0][0], p01 = sred[rowl0][1];
    float2 p10 = sred[rowl0 + 8][0], p11 = sred[rowl0 + 8][1];
    float mu0 = (p00.x + p01.x) * inv, rs0 = rsqrtf((p00.y + p01.y) * inv - mu0 * mu0 + 1e-5f);
    float mu1 = (p10.x + p11.x) * inv, rs1 = rsqrtf((p10.y + p11.y) * inv - mu1 * mu1 + 1e-5f);

    if (r0 < N) {
        float* op = out + (long long)r0 * H;
#pragma unroll
        for (int u = 0; u < 8; ++u) {
            int cb = (wh * 4 + (u >> 1)) * 16 + (u & 1) * 8 + t4 * 2;
            const float2 gg = *reinterpret_cast<const float2*>(gamma + cb);
            const float2 be = *reinterpret_cast<const float2*>(beta + cb);
            float y0 = (acc[u][0] - mu0) * rs0 * gg.x + be.x;
            float y1 = (acc[u][1] - mu0) * rs0 * gg.y + be.y;
            float2 o;
            o.x = fmaxf(y0, 0.f) + log1pf(__expf(-fabsf(y0))) - LN2;
            o.y = fmaxf(y1, 0.f) + log1pf(__expf(-fabsf(y1))) - LN2;
            *reinterpret_cast<float2*>(op + cb) = o;
        }
    }
    if (r1 < N) {
        float* op = out + (long long)r1 * H;
#pragma unroll
        for (int u = 0; u < 8; ++u) {
            int cb = (wh * 4 + (u >> 1)) * 16 + (u & 1) * 8 + t4 * 2;
            const float2 gg = *reinterpret_cast<const float2*>(gamma + cb);
            const float2 be = *reinterpret_cast<const float2*>(beta + cb);
            float y0 = (acc[u][2] - mu1) * rs1 * gg.x + be.x;
            float y1 = (acc[u][3] - mu1) * rs1 * gg.y + be.y;
            float2 o;
            o.x = fmaxf(y0, 0.f) + log1pf(__expf(-fabsf(y0))) - LN2;
            o.y = fmaxf(y1, 0.f) + log1pf(__expf(-fabsf(y1))) - LN2;
            *reinterpret_cast<float2*>(op + cb) = o;
        }
    }
}

// ---------------- launch ----------------
extern "C" void kernel_launch(void* const* d_in, const int* in_sizes, int n_in,
                              void* d_out, int out_size) {
    const float* x   = (const float*)d_in[0];
    const int* ei    = (const int*)d_in[1];
    const float* ea  = (const float*)d_in[2];
    const float* W1  = (const float*)d_in[3];
    const float* b1  = (const float*)d_in[4];
    const float* g1  = (const float*)d_in[5];
    const float* be1 = (const float*)d_in[6];
    const float* W2  = (const float*)d_in[7];
    const float* b2  = (const float*)d_in[8];
    const float* g2  = (const float*)d_in[9];
    const float* be2 = (const float*)d_in[10];
    const float* W3  = (const float*)d_in[11];
    const float* b3  = (const float*)d_in[12];
    const float* g3  = (const float*)d_in[13];
    const float* be3 = (const float*)d_in[14];
    float* out = (float*)d_out;

    int N = in_sizes[0] / H;
    int E = in_sizes[1] / 2;

    float *agg, *h1;
    uint4 *wf1, *wf2, *wf3;
    cudaGetSymbolAddress((void**)&agg, g_agg);
    cudaGetSymbolAddress((void**)&h1, g_h1);
    cudaGetSymbolAddress((void**)&wf1, g_wf1);
    cudaGetSymbolAddress((void**)&wf2, g_wf2);
    cudaGetSymbolAddress((void**)&wf3, g_wf3);

    cudaMemsetAsync(agg, 0, (size_t)N * H * sizeof(float));

    // weight fragment packing (tiny)
    wpack_kernel<<<32, 256>>>(W1, wf1, 256);
    wpack_kernel<<<16, 256>>>(W2, wf2, 128);
    wpack_kernel<<<16, 256>>>(W3, wf3, 128);

    // scatter: 32 lanes per edge (R4 config)
    {
        long long tot = (long long)E * 32;
        int blocks = (int)((tot + 255) / 256);
        scatter_kernel<<<blocks, 256>>>(ea, ei, agg, E);
    }

    int gb = (N + 63) / 64;
    layer_mma<32, true ><<<gb, 256>>>(x,  agg,     wf1, b1, g1, be1, h1,  N);
    layer_mma<16, false><<<gb, 256>>>(h1, nullptr, wf2, b2, g2, be2, agg, N);
    layer_mma<16, false><<<gb, 256>>>(agg, nullptr, wf3, b3, g3, be3, out, N);
}

// round 10
// speedup vs baseline: 1.4308x; 1.4308x over previous
#include <cuda_runtime.h>
#include <cuda_fp16.h>
#include <cstdint>

#define H 128
#define MAXN 102400

// ---------------- scratch (device globals = sanctioned scratch) ----------------
__device__ float  g_agg[(size_t)MAXN * H];
__device__ __half g_h1[(size_t)MAXN * H];
__device__ __half g_h2[(size_t)MAXN * H];
__device__ uint4  g_wf1[16 * 8 * 32];  // K=256: s=16 (k16 steps), u2=8, lane=32 (64KB)
__device__ uint4  g_wf2[8 * 8 * 32];   // K=128 (32KB)
__device__ uint4  g_wf3[8 * 8 * 32];

__device__ __forceinline__ unsigned packh2(float lo, float hi) {
    __half2 h = __floats2half2_rn(lo, hi);
    return *reinterpret_cast<unsigned*>(&h);
}

__device__ __forceinline__ void mma_f16(float c[4], const unsigned a[4], const unsigned b[2]) {
    asm volatile(
        "mma.sync.aligned.m16n8k16.row.col.f32.f16.f16.f32 "
        "{%0,%1,%2,%3}, {%4,%5,%6,%7}, {%8,%9}, {%0,%1,%2,%3};"
        : "+f"(c[0]), "+f"(c[1]), "+f"(c[2]), "+f"(c[3])
        : "r"(a[0]), "r"(a[1]), "r"(a[2]), "r"(a[3]), "r"(b[0]), "r"(b[1]));
}

// ---------------- weight pre-pack: W [K,128] row-major -> fp16 B fragments ----------------
// Wf[(s*8+u2)*32+lane] = {b0(u=2u2), b1(u=2u2), b0(u=2u2+1), b1(u=2u2+1)}
// m16n8k16 col-major B frag, lane l, n-tile u:
//   b0 = {W[s*16+2(l&3)][n], W[s*16+2(l&3)+1][n]},  b1 = same k+8;  n = u*8 + (l>>2)
__global__ void wpack_kernel(const float* __restrict__ W, uint4* __restrict__ Wf, int K) {
    int idx = blockIdx.x * blockDim.x + threadIdx.x;
    int total = (K / 16) * 8 * 32;
    if (idx >= total) return;
    int lane = idx & 31;
    int u2 = (idx >> 5) & 7;
    int s = idx >> 8;
    int n_e = u2 * 16 + (lane >> 2);
    int n_o = n_e + 8;
    int k0 = s * 16 + 2 * (lane & 3);
    uint4 v;
    v.x = packh2(W[(long long)k0 * H + n_e],       W[(long long)(k0 + 1) * H + n_e]);
    v.y = packh2(W[(long long)(k0 + 8) * H + n_e], W[(long long)(k0 + 9) * H + n_e]);
    v.z = packh2(W[(long long)k0 * H + n_o],       W[(long long)(k0 + 1) * H + n_o]);
    v.w = packh2(W[(long long)(k0 + 8) * H + n_o], W[(long long)(k0 + 9) * H + n_o]);
    Wf[idx] = v;
}

// ---------------- scatter: one warp per edge; ea streamed with L2 evict_first policy ----------------
__global__ void scatter_kernel(const float* __restrict__ ea,
                               const int* __restrict__ ei,
                               float* __restrict__ agg, int E) {
    long long idx = (long long)blockIdx.x * blockDim.x + threadIdx.x;
    int e = (int)(idx >> 5);
    if (e >= E) return;
    int c = ((int)idx & 31) << 2;
    int col = ei[E + e];  // edge_index[1][e] (int32)
    unsigned long long pol;
    asm("createpolicy.fractional.L2::evict_first.b64 %0, 1.0;" : "=l"(pol));
    float4 v;
    asm volatile("ld.global.nc.L2::cache_hint.v4.f32 {%0,%1,%2,%3}, [%4], %5;"
                 : "=f"(v.x), "=f"(v.y), "=f"(v.z), "=f"(v.w)
                 : "l"(ea + (long long)e * H + c), "l"(pol));
    float* dst = agg + (long long)col * H + c;
    asm volatile("red.global.add.v4.f32 [%0], {%1, %2, %3, %4};"
                 :: "l"(dst), "f"(v.x), "f"(v.y), "f"(v.z), "f"(v.w) : "memory");
}

// ---------------- fused layer: smem-free fp16 mma GEMM + bias + LN + ssp ----------------
// 256 threads = 8 warps; warp owns 16 rows x all 128 cols (R4 geometry). No smem, no syncs.
// S = K/16 k-steps. HALF_IN: input activations are fp16. HALF_OUT: store fp16.
template <int S, bool CONCAT, bool HALF_IN, bool HALF_OUT>
__global__ __launch_bounds__(256, 2) void layer_mma(
    const void* __restrict__ a0src, const void* __restrict__ a1src,
    const uint4* __restrict__ Wf,
    const float* __restrict__ bias, const float* __restrict__ gamma,
    const float* __restrict__ beta, void* __restrict__ outv, int N) {
    const int tid = threadIdx.x;
    const int w = tid >> 5;
    const int lane = tid & 31;
    const int t4 = lane & 3;
    const int m0 = blockIdx.x * 128 + w * 16;
    const int r0 = m0 + (lane >> 2);
    const int r1 = r0 + 8;
    const long long r0c = (long long)min(r0, N - 1) * H;
    const long long r1c = (long long)min(r1, N - 1) * H;

    float acc[16][4];
#pragma unroll
    for (int u = 0; u < 16; ++u)
#pragma unroll
        for (int j = 0; j < 4; ++j) acc[u][j] = 0.f;

#pragma unroll
    for (int s = 0; s < S; ++s) {
        const void* src;
        int kb;  // element offset within row
        if (CONCAT && s >= 8) { src = a1src; kb = s * 16 - 128; }
        else                  { src = a0src; kb = s * 16; }
        unsigned a[4];
        if (HALF_IN) {
            const __half* hs = (const __half*)src;
            a[0] = __ldg((const unsigned*)(hs + r0c + kb + 2 * t4));
            a[1] = __ldg((const unsigned*)(hs + r1c + kb + 2 * t4));
            a[2] = __ldg((const unsigned*)(hs + r0c + kb + 2 * t4 + 8));
            a[3] = __ldg((const unsigned*)(hs + r1c + kb + 2 * t4 + 8));
        } else {
            const float* fs = (const float*)src;
            float2 f0 = __ldg((const float2*)(fs + r0c + kb + 2 * t4));
            float2 f1 = __ldg((const float2*)(fs + r1c + kb + 2 * t4));
            float2 f2 = __ldg((const float2*)(fs + r0c + kb + 2 * t4 + 8));
            float2 f3 = __ldg((const float2*)(fs + r1c + kb + 2 * t4 + 8));
            a[0] = packh2(f0.x, f0.y);
            a[1] = packh2(f1.x, f1.y);
            a[2] = packh2(f2.x, f2.y);
            a[3] = packh2(f3.x, f3.y);
        }
        const uint4* wf = Wf + (s * 8) * 32 + lane;
#pragma unroll
        for (int u2 = 0; u2 < 8; ++u2) {
            const uint4 bb = __ldg(wf + u2 * 32);
            unsigned b0[2] = {bb.x, bb.y};
            unsigned b1[2] = {bb.z, bb.w};
            mma_f16(acc[u2 * 2], a, b0);
            mma_f16(acc[u2 * 2 + 1], a, b1);
        }
    }

    // ---- epilogue: bias + per-row LN (quad shuffle) + shifted softplus ----
    const float LN2 = 0.69314718055994531f;
    const float inv = 1.f / (float)H;
    float s1a = 0.f, s2a = 0.f, s1b = 0.f, s2b = 0.f;
#pragma unroll
    for (int u = 0; u < 16; ++u) {
        int cb = u * 8 + t4 * 2;
        const float2 b2 = *reinterpret_cast<const float2*>(bias + cb);
        acc[u][0] += b2.x; acc[u][1] += b2.y;
        acc[u][2] += b2.x; acc[u][3] += b2.y;
        s1a += acc[u][0] + acc[u][1];
        s2a += acc[u][0] * acc[u][0] + acc[u][1] * acc[u][1];
        s1b += acc[u][2] + acc[u][3];
        s2b += acc[u][2] * acc[u][2] + acc[u][3] * acc[u][3];
    }
#pragma unroll
    for (int off = 1; off <= 2; off <<= 1) {
        s1a += __shfl_xor_sync(0xffffffffu, s1a, off);
        s2a += __shfl_xor_sync(0xffffffffu, s2a, off);
        s1b += __shfl_xor_sync(0xffffffffu, s1b, off);
        s2b += __shfl_xor_sync(0xffffffffu, s2b, off);
    }
    float mu0 = s1a * inv, rs0 = rsqrtf(s2a * inv - mu0 * mu0 + 1e-5f);
    float mu1 = s1b * inv, rs1 = rsqrtf(s2b * inv - mu1 * mu1 + 1e-5f);

#pragma unroll
    for (int half = 0; half < 2; ++half) {
        int r = half ? r1 : r0;
        float mu = half ? mu1 : mu0;
        float rs = half ? rs1 : rs0;
        if (r < N) {
#pragma unroll
            for (int u = 0; u < 16; ++u) {
                int cb = u * 8 + t4 * 2;
                const float2 gg = *reinterpret_cast<const float2*>(gamma + cb);
                const float2 be = *reinterpret_cast<const float2*>(beta + cb);
                float y0 = (acc[u][half * 2 + 0] - mu) * rs * gg.x + be.x;
                float y1 = (acc[u][half * 2 + 1] - mu) * rs * gg.y + be.y;
                float o0 = fmaxf(y0, 0.f) + log1pf(__expf(-fabsf(y0))) - LN2;
                float o1 = fmaxf(y1, 0.f) + log1pf(__expf(-fabsf(y1))) - LN2;
                if (HALF_OUT) {
                    __half* op = (__half*)outv + (long long)r * H;
                    *reinterpret_cast<__half2*>(op + cb) = __floats2half2_rn(o0, o1);
                } else {
                    float* op = (float*)outv + (long long)r * H;
                    *reinterpret_cast<float2*>(op + cb) = make_float2(o0, o1);
                }
            }
        }
    }
}

// ---------------- launch ----------------
extern "C" void kernel_launch(void* const* d_in, const int* in_sizes, int n_in,
                              void* d_out, int out_size) {
    const float* x   = (const float*)d_in[0];
    const int* ei    = (const int*)d_in[1];
    const float* ea  = (const float*)d_in[2];
    const float* W1  = (const float*)d_in[3];
    const float* b1  = (const float*)d_in[4];
    const float* g1  = (const float*)d_in[5];
    const float* be1 = (const float*)d_in[6];
    const float* W2  = (const float*)d_in[7];
    const float* b2  = (const float*)d_in[8];
    const float* g2  = (const float*)d_in[9];
    const float* be2 = (const float*)d_in[10];
    const float* W3  = (const float*)d_in[11];
    const float* b3  = (const float*)d_in[12];
    const float* g3  = (const float*)d_in[13];
    const float* be3 = (const float*)d_in[14];
    float* out = (float*)d_out;

    int N = in_sizes[0] / H;
    int E = in_sizes[1] / 2;

    float* agg;
    __half *h1, *h2;
    uint4 *wf1, *wf2, *wf3;
    cudaGetSymbolAddress((void**)&agg, g_agg);
    cudaGetSymbolAddress((void**)&h1, g_h1);
    cudaGetSymbolAddress((void**)&h2, g_h2);
    cudaGetSymbolAddress((void**)&wf1, g_wf1);
    cudaGetSymbolAddress((void**)&wf2, g_wf2);
    cudaGetSymbolAddress((void**)&wf3, g_wf3);

    cudaMemsetAsync(agg, 0, (size_t)N * H * sizeof(float));

    // weight fragment packing (tiny)
    wpack_kernel<<<16, 256>>>(W1, wf1, 256);
    wpack_kernel<<<8, 256>>>(W2, wf2, 128);
    wpack_kernel<<<8, 256>>>(W3, wf3, 128);

    // scatter: 32 lanes per edge
    {
        long long tot = (long long)E * 32;
        int blocks = (int)((tot + 255) / 256);
        scatter_kernel<<<blocks, 256>>>(ea, ei, agg, E);
    }

    int gb = (N + 127) / 128;
    layer_mma<16, true,  false, true ><<<gb, 256>>>(x,  agg,     wf1, b1, g1, be1, h1,  N);
    layer_mma<8,  false, true,  true ><<<gb, 256>>>(h1, nullptr, wf2, b2, g2, be2, h2,  N);
    layer_mma<8,  false, true,  false><<<gb, 256>>>(h2, nullptr, wf3, b3, g3, be3, out, N);
}

// round 11
// speedup vs baseline: 1.4791x; 1.0338x over previous
#include <cuda_runtime.h>
#include <cuda_fp16.h>
#include <cstdint>

#define H 128
#define MAXN 102400

// ---------------- scratch (device globals = sanctioned scratch) ----------------
__device__ float  g_agg[(size_t)MAXN * H];
__device__ __half g_h1[(size_t)MAXN * H];
__device__ __half g_h2[(size_t)MAXN * H];
__device__ uint4  g_wf1[16 * 8 * 32];  // K=256: s=16 (k16 steps), u2=8, lane=32 (64KB)
__device__ uint4  g_wf2[8 * 8 * 32];   // K=128 (32KB)
__device__ uint4  g_wf3[8 * 8 * 32];

__device__ __forceinline__ unsigned packh2(float lo, float hi) {
    __half2 h = __floats2half2_rn(lo, hi);
    return *reinterpret_cast<unsigned*>(&h);
}

__device__ __forceinline__ void mma_f16(float c[4], const unsigned a[4], const unsigned b[2]) {
    asm volatile(
        "mma.sync.aligned.m16n8k16.row.col.f32.f16.f16.f32 "
        "{%0,%1,%2,%3}, {%4,%5,%6,%7}, {%8,%9}, {%0,%1,%2,%3};"
        : "+f"(c[0]), "+f"(c[1]), "+f"(c[2]), "+f"(c[3])
        : "r"(a[0]), "r"(a[1]), "r"(a[2]), "r"(a[3]), "r"(b[0]), "r"(b[1]));
}

// ---------------- merged weight pre-pack with K-permutation ----------------
// Permutation kappa (applied to BOTH A and B): for lane quad t4,
// frag-k {2t4, 2t4+1, 2t4+8, 2t4+9}  ->  real-k {4t4, 4t4+1, 4t4+2, 4t4+3}.
// So B frag lane l (t4=l&3, n=l>>2), real k0 = s*16 + 4*t4:
//   b0 = {W[k0][n],   W[k0+1][n]},  b1 = {W[k0+2][n], W[k0+3][n]}
__device__ __forceinline__ void wpack_one(const float* __restrict__ W,
                                          uint4* __restrict__ Wf, int idx) {
    int lane = idx & 31;
    int u2 = (idx >> 5) & 7;
    int s = idx >> 8;
    int n_e = u2 * 16 + (lane >> 2);
    int n_o = n_e + 8;
    int k0 = s * 16 + 4 * (lane & 3);
    uint4 v;
    v.x = packh2(W[(long long)k0 * H + n_e],       W[(long long)(k0 + 1) * H + n_e]);
    v.y = packh2(W[(long long)(k0 + 2) * H + n_e], W[(long long)(k0 + 3) * H + n_e]);
    v.z = packh2(W[(long long)k0 * H + n_o],       W[(long long)(k0 + 1) * H + n_o]);
    v.w = packh2(W[(long long)(k0 + 2) * H + n_o], W[(long long)(k0 + 3) * H + n_o]);
    Wf[idx] = v;
}

__global__ void wpack_all(const float* __restrict__ W1, uint4* __restrict__ Wf1,
                          const float* __restrict__ W2, uint4* __restrict__ Wf2,
                          const float* __restrict__ W3, uint4* __restrict__ Wf3) {
    int b = blockIdx.x;
    int t = threadIdx.x;
    if (b < 16)      wpack_one(W1, Wf1, b * 256 + t);
    else if (b < 24) wpack_one(W2, Wf2, (b - 16) * 256 + t);
    else             wpack_one(W3, Wf3, (b - 24) * 256 + t);
}

// ---------------- scatter: one warp per edge; ea streamed with L2 evict_first policy ----------------
__global__ void scatter_kernel(const float* __restrict__ ea,
                               const int* __restrict__ ei,
                               float* __restrict__ agg, int E) {
    long long idx = (long long)blockIdx.x * blockDim.x + threadIdx.x;
    int e = (int)(idx >> 5);
    if (e >= E) return;
    int c = ((int)idx & 31) << 2;
    int col = ei[E + e];  // edge_index[1][e] (int32)
    unsigned long long pol;
    asm("createpolicy.fractional.L2::evict_first.b64 %0, 1.0;" : "=l"(pol));
    float4 v;
    asm volatile("ld.global.nc.L2::cache_hint.v4.f32 {%0,%1,%2,%3}, [%4], %5;"
                 : "=f"(v.x), "=f"(v.y), "=f"(v.z), "=f"(v.w)
                 : "l"(ea + (long long)e * H + c), "l"(pol));
    float* dst = agg + (long long)col * H + c;
    asm volatile("red.global.add.v4.f32 [%0], {%1, %2, %3, %4};"
                 :: "l"(dst), "f"(v.x), "f"(v.y), "f"(v.z), "f"(v.w) : "memory");
}

// ---------------- fused layer: smem-free fp16 mma GEMM + bias + LN + ssp ----------------
// 256 threads = 8 warps; warp owns 16 rows x all 128 cols. No smem, no syncs.
// K-permuted A fragments: one 8B (fp16) / 16B (fp32) load per row per k16 step.
template <int S, bool CONCAT, bool HALF_IN, bool HALF_OUT>
__global__ __launch_bounds__(256, 2) void layer_mma(
    const void* __restrict__ a0src, const void* __restrict__ a1src,
    const uint4* __restrict__ Wf,
    const float* __restrict__ bias, const float* __restrict__ gamma,
    const float* __restrict__ beta, void* __restrict__ outv, int N) {
    const int tid = threadIdx.x;
    const int w = tid >> 5;
    const int lane = tid & 31;
    const int t4 = lane & 3;
    const int m0 = blockIdx.x * 128 + w * 16;
    const int r0 = m0 + (lane >> 2);
    const int r1 = r0 + 8;
    const long long r0c = (long long)min(r0, N - 1) * H;
    const long long r1c = (long long)min(r1, N - 1) * H;

    float acc[16][4];
#pragma unroll
    for (int u = 0; u < 16; ++u)
#pragma unroll
        for (int j = 0; j < 4; ++j) acc[u][j] = 0.f;

#pragma unroll
    for (int s = 0; s < S; ++s) {
        const void* src;
        int kb;  // element offset within row
        if (CONCAT && s >= 8) { src = a1src; kb = s * 16 - 128; }
        else                  { src = a0src; kb = s * 16; }
        unsigned a[4];
        if (HALF_IN) {
            const __half* hs = (const __half*)src;
            const uint2 q0 = __ldg((const uint2*)(hs + r0c + kb + 4 * t4));
            const uint2 q1 = __ldg((const uint2*)(hs + r1c + kb + 4 * t4));
            a[0] = q0.x; a[2] = q0.y;
            a[1] = q1.x; a[3] = q1.y;
        } else {
            const float* fs = (const float*)src;
            const float4 f0 = __ldg((const float4*)(fs + r0c + kb + 4 * t4));
            const float4 f1 = __ldg((const float4*)(fs + r1c + kb + 4 * t4));
            a[0] = packh2(f0.x, f0.y); a[2] = packh2(f0.z, f0.w);
            a[1] = packh2(f1.x, f1.y); a[3] = packh2(f1.z, f1.w);
        }
        const uint4* wf = Wf + (s * 8) * 32 + lane;
#pragma unroll
        for (int u2 = 0; u2 < 8; ++u2) {
            const uint4 bb = __ldg(wf + u2 * 32);
            unsigned b0[2] = {bb.x, bb.y};
            unsigned b1[2] = {bb.z, bb.w};
            mma_f16(acc[u2 * 2], a, b0);
            mma_f16(acc[u2 * 2 + 1], a, b1);
        }
    }

    // ---- epilogue: bias + per-row LN (quad shuffle) + shifted softplus ----
    const float LN2 = 0.69314718055994531f;
    const float inv = 1.f / (float)H;
    float s1a = 0.f, s2a = 0.f, s1b = 0.f, s2b = 0.f;
#pragma unroll
    for (int u = 0; u < 16; ++u) {
        int cb = u * 8 + t4 * 2;
        const float2 b2 = *reinterpret_cast<const float2*>(bias + cb);
        acc[u][0] += b2.x; acc[u][1] += b2.y;
        acc[u][2] += b2.x; acc[u][3] += b2.y;
        s1a += acc[u][0] + acc[u][1];
        s2a += acc[u][0] * acc[u][0] + acc[u][1] * acc[u][1];
        s1b += acc[u][2] + acc[u][3];
        s2b += acc[u][2] * acc[u][2] + acc[u][3] * acc[u][3];
    }
#pragma unroll
    for (int off = 1; off <= 2; off <<= 1) {
        s1a += __shfl_xor_sync(0xffffffffu, s1a, off);
        s2a += __shfl_xor_sync(0xffffffffu, s2a, off);
        s1b += __shfl_xor_sync(0xffffffffu, s1b, off);
        s2b += __shfl_xor_sync(0xffffffffu, s2b, off);
    }
    float mu0 = s1a * inv, rs0 = rsqrtf(s2a * inv - mu0 * mu0 + 1e-5f);
    float mu1 = s1b * inv, rs1 = rsqrtf(s2b * inv - mu1 * mu1 + 1e-5f);

#pragma unroll
    for (int half = 0; half < 2; ++half) {
        int r = half ? r1 : r0;
        float mu = half ? mu1 : mu0;
        float rs = half ? rs1 : rs0;
        if (r < N) {
#pragma unroll
            for (int u = 0; u < 16; ++u) {
                int cb = u * 8 + t4 * 2;
                const float2 gg = *reinterpret_cast<const float2*>(gamma + cb);
                const float2 be = *reinterpret_cast<const float2*>(beta + cb);
                float y0 = (acc[u][half * 2 + 0] - mu) * rs * gg.x + be.x;
                float y1 = (acc[u][half * 2 + 1] - mu) * rs * gg.y + be.y;
                float o0 = fmaxf(y0, 0.f) + log1pf(__expf(-fabsf(y0))) - LN2;
                float o1 = fmaxf(y1, 0.f) + log1pf(__expf(-fabsf(y1))) - LN2;
                if (HALF_OUT) {
                    __half* op = (__half*)outv + (long long)r * H;
                    *reinterpret_cast<__half2*>(op + cb) = __floats2half2_rn(o0, o1);
                } else {
                    float* op = (float*)outv + (long long)r * H;
                    *reinterpret_cast<float2*>(op + cb) = make_float2(o0, o1);
                }
            }
        }
    }
}

// ---------------- launch ----------------
extern "C" void kernel_launch(void* const* d_in, const int* in_sizes, int n_in,
                              void* d_out, int out_size) {
    const float* x   = (const float*)d_in[0];
    const int* ei    = (const int*)d_in[1];
    const float* ea  = (const float*)d_in[2];
    const float* W1  = (const float*)d_in[3];
    const float* b1  = (const float*)d_in[4];
    const float* g1  = (const float*)d_in[5];
    const float* be1 = (const float*)d_in[6];
    const float* W2  = (const float*)d_in[7];
    const float* b2  = (const float*)d_in[8];
    const float* g2  = (const float*)d_in[9];
    const float* be2 = (const float*)d_in[10];
    const float* W3  = (const float*)d_in[11];
    const float* b3  = (const float*)d_in[12];
    const float* g3  = (const float*)d_in[13];
    const float* be3 = (const float*)d_in[14];
    float* out = (float*)d_out;

    int N = in_sizes[0] / H;
    int E = in_sizes[1] / 2;

    float* agg;
    __half *h1, *h2;
    uint4 *wf1, *wf2, *wf3;
    cudaGetSymbolAddress((void**)&agg, g_agg);
    cudaGetSymbolAddress((void**)&h1, g_h1);
    cudaGetSymbolAddress((void**)&h2, g_h2);
    cudaGetSymbolAddress((void**)&wf1, g_wf1);
    cudaGetSymbolAddress((void**)&wf2, g_wf2);
    cudaGetSymbolAddress((void**)&wf3, g_wf3);

    cudaMemsetAsync(agg, 0, (size_t)N * H * sizeof(float));

    // single merged weight pre-pack launch
    wpack_all<<<32, 256>>>(W1, wf1, W2, wf2, W3, wf3);

    // scatter: 32 lanes per edge
    {
        long long tot = (long long)E * 32;
        int blocks = (int)((tot + 255) / 256);
        scatter_kernel<<<blocks, 256>>>(ea, ei, agg, E);
    }

    int gb = (N + 127) / 128;
    layer_mma<16, true,  false, true ><<<gb, 256>>>(x,  agg,     wf1, b1, g1, be1, h1,  N);
    layer_mma<8,  false, true,  true ><<<gb, 256>>>(h1, nullptr, wf2, b2, g2, be2, h2,  N);
    layer_mma<8,  false, true,  false><<<gb, 256>>>(h2, nullptr, wf3, b3, g3, be3, out, N);
}

// round 12
// speedup vs baseline: 1.6848x; 1.1390x over previous
#include <cuda_runtime.h>
#include <cuda_fp16.h>
#include <cstdint>

#define H 128
#define MAXN 102400

// ---------------- scratch (device globals = sanctioned scratch) ----------------
__device__ float  g_agg[(size_t)MAXN * H];
__device__ __half g_h1[(size_t)MAXN * H];
__device__ __half g_h2[(size_t)MAXN * H];
__device__ uint4  g_wf1[16 * 8 * 32];  // K=256: s=16 (k16 steps), u2=8, lane=32 (64KB)
__device__ uint4  g_wf2[8 * 8 * 32];   // K=128 (32KB)
__device__ uint4  g_wf3[8 * 8 * 32];

__device__ __forceinline__ unsigned packh2(float lo, float hi) {
    __half2 h = __floats2half2_rn(lo, hi);
    return *reinterpret_cast<unsigned*>(&h);
}

__device__ __forceinline__ void mma_f16(float c[4], const unsigned a[4], const unsigned b[2]) {
    asm volatile(
        "mma.sync.aligned.m16n8k16.row.col.f32.f16.f16.f32 "
        "{%0,%1,%2,%3}, {%4,%5,%6,%7}, {%8,%9}, {%0,%1,%2,%3};"
        : "+f"(c[0]), "+f"(c[1]), "+f"(c[2]), "+f"(c[3])
        : "r"(a[0]), "r"(a[1]), "r"(a[2]), "r"(a[3]), "r"(b[0]), "r"(b[1]));
}

// Fast shifted softplus: ssp(y) = max(y,0) + ln((1 + e^{-|y|}) / 2)
//                              = max(y,0) + (log2(1 + e^{-|y|}) - 1) * ln2
__device__ __forceinline__ float ssp_fast(float y) {
    const float LN2 = 0.69314718055994531f;
    float t = __expf(-fabsf(y));          // FMUL + MUFU.EX2
    float l = __log2f(1.f + t);           // FADD + MUFU.LG2
    return fmaf(l - 1.f, LN2, fmaxf(y, 0.f));
}

// ---------------- merged weight pre-pack with K-permutation ----------------
// kappa (applied to BOTH A and B): frag-k {2t4,2t4+1,2t4+8,2t4+9} -> real-k {4t4..4t4+3}
__device__ __forceinline__ void wpack_one(const float* __restrict__ W,
                                          uint4* __restrict__ Wf, int idx) {
    int lane = idx & 31;
    int u2 = (idx >> 5) & 7;
    int s = idx >> 8;
    int n_e = u2 * 16 + (lane >> 2);
    int n_o = n_e + 8;
    int k0 = s * 16 + 4 * (lane & 3);
    uint4 v;
    v.x = packh2(W[(long long)k0 * H + n_e],       W[(long long)(k0 + 1) * H + n_e]);
    v.y = packh2(W[(long long)(k0 + 2) * H + n_e], W[(long long)(k0 + 3) * H + n_e]);
    v.z = packh2(W[(long long)k0 * H + n_o],       W[(long long)(k0 + 1) * H + n_o]);
    v.w = packh2(W[(long long)(k0 + 2) * H + n_o], W[(long long)(k0 + 3) * H + n_o]);
    Wf[idx] = v;
}

__global__ void wpack_all(const float* __restrict__ W1, uint4* __restrict__ Wf1,
                          const float* __restrict__ W2, uint4* __restrict__ Wf2,
                          const float* __restrict__ W3, uint4* __restrict__ Wf3) {
    int b = blockIdx.x;
    int t = threadIdx.x;
    if (b < 16)      wpack_one(W1, Wf1, b * 256 + t);
    else if (b < 24) wpack_one(W2, Wf2, (b - 16) * 256 + t);
    else             wpack_one(W3, Wf3, (b - 24) * 256 + t);
}

// ---------------- scatter: one warp per edge; ea streamed with L2 evict_first policy ----------------
__global__ void scatter_kernel(const float* __restrict__ ea,
                               const int* __restrict__ ei,
                               float* __restrict__ agg, int E) {
    long long idx = (long long)blockIdx.x * blockDim.x + threadIdx.x;
    int e = (int)(idx >> 5);
    if (e >= E) return;
    int c = ((int)idx & 31) << 2;
    int col = ei[E + e];  // edge_index[1][e] (int32)
    unsigned long long pol;
    asm("createpolicy.fractional.L2::evict_first.b64 %0, 1.0;" : "=l"(pol));
    float4 v;
    asm volatile("ld.global.nc.L2::cache_hint.v4.f32 {%0,%1,%2,%3}, [%4], %5;"
                 : "=f"(v.x), "=f"(v.y), "=f"(v.z), "=f"(v.w)
                 : "l"(ea + (long long)e * H + c), "l"(pol));
    float* dst = agg + (long long)col * H + c;
    asm volatile("red.global.add.v4.f32 [%0], {%1, %2, %3, %4};"
                 :: "l"(dst), "f"(v.x), "f"(v.y), "f"(v.z), "f"(v.w) : "memory");
}

// ---------------- fused layer: smem-free fp16 mma GEMM + bias + LN + ssp ----------------
// 256 threads = 8 warps; warp owns 16 rows x all 128 cols. No smem, no syncs.
template <int S, bool CONCAT, bool HALF_IN, bool HALF_OUT>
__global__ __launch_bounds__(256, 2) void layer_mma(
    const void* __restrict__ a0src, const void* __restrict__ a1src,
    const uint4* __restrict__ Wf,
    const float* __restrict__ bias, const float* __restrict__ gamma,
    const float* __restrict__ beta, void* __restrict__ outv, int N) {
    const int tid = threadIdx.x;
    const int w = tid >> 5;
    const int lane = tid & 31;
    const int t4 = lane & 3;
    const int m0 = blockIdx.x * 128 + w * 16;
    const int r0 = m0 + (lane >> 2);
    const int r1 = r0 + 8;
    const long long r0c = (long long)min(r0, N - 1) * H;
    const long long r1c = (long long)min(r1, N - 1) * H;

    float acc[16][4];
#pragma unroll
    for (int u = 0; u < 16; ++u)
#pragma unroll
        for (int j = 0; j < 4; ++j) acc[u][j] = 0.f;

#pragma unroll
    for (int s = 0; s < S; ++s) {
        const void* src;
        int kb;  // element offset within row
        if (CONCAT && s >= 8) { src = a1src; kb = s * 16 - 128; }
        else                  { src = a0src; kb = s * 16; }
        unsigned a[4];
        if (HALF_IN) {
            const __half* hs = (const __half*)src;
            const uint2 q0 = __ldg((const uint2*)(hs + r0c + kb + 4 * t4));
            const uint2 q1 = __ldg((const uint2*)(hs + r1c + kb + 4 * t4));
            a[0] = q0.x; a[2] = q0.y;
            a[1] = q1.x; a[3] = q1.y;
        } else {
            const float* fs = (const float*)src;
            const float4 f0 = __ldg((const float4*)(fs + r0c + kb + 4 * t4));
            const float4 f1 = __ldg((const float4*)(fs + r1c + kb + 4 * t4));
            a[0] = packh2(f0.x, f0.y); a[2] = packh2(f0.z, f0.w);
            a[1] = packh2(f1.x, f1.y); a[3] = packh2(f1.z, f1.w);
        }
        const uint4* wf = Wf + (s * 8) * 32 + lane;
#pragma unroll
        for (int u2 = 0; u2 < 8; ++u2) {
            const uint4 bb = __ldg(wf + u2 * 32);
            unsigned b0[2] = {bb.x, bb.y};
            unsigned b1[2] = {bb.z, bb.w};
            mma_f16(acc[u2 * 2], a, b0);
            mma_f16(acc[u2 * 2 + 1], a, b1);
        }
    }

    // ---- epilogue: bias + per-row LN (quad shuffle) + fast ssp ----
    const float inv = 1.f / (float)H;
    float s1a = 0.f, s2a = 0.f, s1b = 0.f, s2b = 0.f;
#pragma unroll
    for (int u = 0; u < 16; ++u) {
        int cb = u * 8 + t4 * 2;
        const float2 b2 = *reinterpret_cast<const float2*>(bias + cb);
        acc[u][0] += b2.x; acc[u][1] += b2.y;
        acc[u][2] += b2.x; acc[u][3] += b2.y;
        s1a += acc[u][0] + acc[u][1];
        s2a += acc[u][0] * acc[u][0] + acc[u][1] * acc[u][1];
        s1b += acc[u][2] + acc[u][3];
        s2b += acc[u][2] * acc[u][2] + acc[u][3] * acc[u][3];
    }
#pragma unroll
    for (int off = 1; off <= 2; off <<= 1) {
        s1a += __shfl_xor_sync(0xffffffffu, s1a, off);
        s2a += __shfl_xor_sync(0xffffffffu, s2a, off);
        s1b += __shfl_xor_sync(0xffffffffu, s1b, off);
        s2b += __shfl_xor_sync(0xffffffffu, s2b, off);
    }
    float mu0 = s1a * inv, rs0 = rsqrtf(s2a * inv - mu0 * mu0 + 1e-5f);
    float mu1 = s1b * inv, rs1 = rsqrtf(s2b * inv - mu1 * mu1 + 1e-5f);

    const bool v0 = (r0 < N), v1 = (r1 < N);
#pragma unroll
    for (int u = 0; u < 16; ++u) {
        int cb = u * 8 + t4 * 2;
        const float2 gg = *reinterpret_cast<const float2*>(gamma + cb);
        const float2 be = *reinterpret_cast<const float2*>(beta + cb);
        if (v0) {
            float y0 = (acc[u][0] - mu0) * rs0 * gg.x + be.x;
            float y1 = (acc[u][1] - mu0) * rs0 * gg.y + be.y;
            float o0 = ssp_fast(y0), o1 = ssp_fast(y1);
            if (HALF_OUT)
                *reinterpret_cast<__half2*>((__half*)outv + (long long)r0 * H + cb) =
                    __floats2half2_rn(o0, o1);
            else
                *reinterpret_cast<float2*>((float*)outv + (long long)r0 * H + cb) =
                    make_float2(o0, o1);
        }
        if (v1) {
            float y0 = (acc[u][2] - mu1) * rs1 * gg.x + be.x;
            float y1 = (acc[u][3] - mu1) * rs1 * gg.y + be.y;
            float o0 = ssp_fast(y0), o1 = ssp_fast(y1);
            if (HALF_OUT)
                *reinterpret_cast<__half2*>((__half*)outv + (long long)r1 * H + cb) =
                    __floats2half2_rn(o0, o1);
            else
                *reinterpret_cast<float2*>((float*)outv + (long long)r1 * H + cb) =
                    make_float2(o0, o1);
        }
    }
}

// ---------------- launch ----------------
extern "C" void kernel_launch(void* const* d_in, const int* in_sizes, int n_in,
                              void* d_out, int out_size) {
    const float* x   = (const float*)d_in[0];
    const int* ei    = (const int*)d_in[1];
    const float* ea  = (const float*)d_in[2];
    const float* W1  = (const float*)d_in[3];
    const float* b1  = (const float*)d_in[4];
    const float* g1  = (const float*)d_in[5];
    const float* be1 = (const float*)d_in[6];
    const float* W2  = (const float*)d_in[7];
    const float* b2  = (const float*)d_in[8];
    const float* g2  = (const float*)d_in[9];
    const float* be2 = (const float*)d_in[10];
    const float* W3  = (const float*)d_in[11];
    const float* b3  = (const float*)d_in[12];
    const float* g3  = (const float*)d_in[13];
    const float* be3 = (const float*)d_in[14];
    float* out = (float*)d_out;

    int N = in_sizes[0] / H;
    int E = in_sizes[1] / 2;

    float* agg;
    __half *h1, *h2;
    uint4 *wf1, *wf2, *wf3;
    cudaGetSymbolAddress((void**)&agg, g_agg);
    cudaGetSymbolAddress((void**)&h1, g_h1);
    cudaGetSymbolAddress((void**)&h2, g_h2);
    cudaGetSymbolAddress((void**)&wf1, g_wf1);
    cudaGetSymbolAddress((void**)&wf2, g_wf2);
    cudaGetSymbolAddress((void**)&wf3, g_wf3);

    cudaMemsetAsync(agg, 0, (size_t)N * H * sizeof(float));

    // single merged weight pre-pack launch
    wpack_all<<<32, 256>>>(W1, wf1, W2, wf2, W3, wf3);

    // scatter: 32 lanes per edge
    {
        long long tot = (long long)E * 32;
        int blocks = (int)((tot + 255) / 256);
        scatter_kernel<<<blocks, 256>>>(ea, ei, agg, E);
    }

    int gb = (N + 127) / 128;
    layer_mma<16, true,  false, true ><<<gb, 256>>>(x,  agg,     wf1, b1, g1, be1, h1,  N);
    layer_mma<8,  false, true,  true ><<<gb, 256>>>(h1, nullptr, wf2, b2, g2, be2, h2,  N);
    layer_mma<8,  false, true,  false><<<gb, 256>>>(h2, nullptr, wf3, b3, g3, be3, out, N);
}